// round 16
// baseline (speedup 1.0000x reference)
#include <cuda_runtime.h>
#include <cstdint>

// out[0:100]   = dot(I[row,:], p), row = inds1[m,0]*28 + inds1[m,1]
// out[100:200] = dot(J[row,:], p), P = 50000.
//
// v14: TMA pipeline combining v12's depth with v8's occupancy:
// 200 blocks (SPLIT=4) x 512 thr, occ 2, RING=3 (2-stage lookahead),
// 7KB bulk copies, 5 streams/block (4 rows + p). ~14MB in flight chip-wide.
// Global-ticket fused reduction (the best-performing completion scheme).

#define P_DIM     50000
#define P_VEC4    (P_DIM / 4)       // 12500 float4 per row
#define SPLIT     4
#define CHUNK4    (P_VEC4 / SPLIT)  // 3125 float4 per stream per block
#define STAGE4    448               // float4 per stream per stage (7KB)
#define NSTAGES   7                 // 6*448 + 437
#define LAST4     (CHUNK4 - (NSTAGES - 1) * STAGE4)  // 437
#define CARD2     100
#define NOUT      200
#define RPB       4
#define NGROUPS   (NOUT / RPB)      // 50
#define NBLOCKS   (NGROUPS * SPLIT) // 200  (<= 296 conc @ occ 2 -> one wave)
#define W_IMG     28
#define NTHREADS  512
#define NWARPS    16
#define NSTREAMS  (RPB + 1)
#define RING      3
#define STAGE_BYTES (STAGE4 * 16)               // 7168 B per stream
#define BUF_BYTES   (NSTREAMS * STAGE_BYTES)    // 35840 B per stage
#define SMEM_DYN    (RING * BUF_BYTES)          // 107520 B -> 2 CTAs/SM

__device__ float        g_partials[NOUT * SPLIT];
__device__ unsigned int g_ticket = 0;

__device__ __forceinline__ uint32_t smem_u32(const void* p) {
    uint32_t a;
    asm("{ .reg .u64 t; cvta.to.shared.u64 t, %1; cvt.u32.u64 %0, t; }"
        : "=r"(a) : "l"(p));
    return a;
}
__device__ __forceinline__ void mbar_init(uint32_t bar, uint32_t cnt) {
    asm volatile("mbarrier.init.shared.b64 [%0], %1;" :: "r"(bar), "r"(cnt) : "memory");
}
__device__ __forceinline__ void mbar_expect_tx(uint32_t bar, uint32_t bytes) {
    asm volatile("mbarrier.arrive.expect_tx.shared.b64 _, [%0], %1;"
                 :: "r"(bar), "r"(bytes) : "memory");
}
__device__ __forceinline__ void mbar_wait(uint32_t bar, uint32_t parity) {
    uint32_t done;
    asm volatile(
        "{ .reg .pred p;\n"
        "  mbarrier.try_wait.parity.acquire.cta.shared::cta.b64 p, [%1], %2;\n"
        "  selp.b32 %0, 1, 0, p; }"
        : "=r"(done) : "r"(bar), "r"(parity) : "memory");
    if (!done) {
        asm volatile(
            "{ .reg .pred P1;\n"
            "WAIT_%=:\n"
            "  mbarrier.try_wait.parity.acquire.cta.shared::cta.b64 P1, [%0], %1, 0x989680;\n"
            "  @P1 bra.uni DONE_%=;\n"
            "  bra.uni WAIT_%=;\n"
            "DONE_%=: }"
            :: "r"(bar), "r"(parity) : "memory");
    }
}
__device__ __forceinline__ void bulk_g2s(uint32_t dst, const void* src,
                                         uint32_t bytes, uint32_t bar) {
    asm volatile(
        "cp.async.bulk.shared::cta.global.mbarrier::complete_tx::bytes "
        "[%0], [%1], %2, [%3];"
        :: "r"(dst), "l"(src), "r"(bytes), "r"(bar) : "memory");
}

__global__ __launch_bounds__(NTHREADS, 2)
void gather_dot_v14(const float* __restrict__ p,
                    const float* __restrict__ I,
                    const float* __restrict__ J,
                    const int*   __restrict__ inds1,
                    const int*   __restrict__ inds2,
                    float*       __restrict__ out)
{
    extern __shared__ __align__(128) unsigned char smem[];
    __shared__ __align__(8) uint64_t mbar_storage[RING];
    __shared__ float ws[RPB][NWARPS];
    __shared__ bool  s_last;

    const int tid   = threadIdx.x;
    const int group = blockIdx.x / SPLIT;   // 0..49
    const int chunk = blockIdx.x % SPLIT;   // 0..3
    const int mbase = group * RPB;          // never straddles the I/J boundary

    const float* mat;
    const int*   ind;
    if (mbase < CARD2) { mat = I; ind = inds1 + 2 * mbase; }
    else               { mat = J; ind = inds2 + 2 * (mbase - CARD2); }

    const uint32_t sbase = smem_u32(smem);
    uint32_t bar[RING];
    #pragma unroll
    for (int k = 0; k < RING; k++) bar[k] = smem_u32(&mbar_storage[k]);

    if (tid == 0) {
        #pragma unroll
        for (int k = 0; k < RING; k++) mbar_init(bar[k], 1);
    }
    __syncthreads();

    const char* src[NSTREAMS];
    #pragma unroll
    for (int k = 0; k < RPB; k++) {
        int row = ind[2 * k] * W_IMG + ind[2 * k + 1];
        src[k] = (const char*)(mat + (size_t)row * P_DIM) + (size_t)chunk * CHUNK4 * 16;
    }
    src[RPB] = (const char*)p + (size_t)chunk * CHUNK4 * 16;

    auto issue = [&](int s) {
        const int      len   = (s == NSTAGES - 1) ? LAST4 : STAGE4;
        const uint32_t bytes = (uint32_t)len * 16u;
        const int      slot  = s % RING;
        const uint32_t dst0  = sbase + (uint32_t)slot * BUF_BYTES;
        mbar_expect_tx(bar[slot], bytes * NSTREAMS);
        #pragma unroll
        for (int k = 0; k < NSTREAMS; k++)
            bulk_g2s(dst0 + k * STAGE_BYTES, src[k] + (size_t)s * STAGE_BYTES,
                     bytes, bar[slot]);
    };

    if (tid == 0) { issue(0); issue(1); issue(2); }

    float s0 = 0.0f, s1 = 0.0f, s2 = 0.0f, s3 = 0.0f;

    for (int s = 0; s < NSTAGES; s++) {
        const int slot   = s % RING;
        const int parity = (s / RING) & 1;
        mbar_wait(bar[slot], parity);

        const int len = (s == NSTAGES - 1) ? LAST4 : STAGE4;
        const float4* buf = reinterpret_cast<const float4*>(smem + slot * BUF_BYTES);
        for (int i = tid; i < len; i += NTHREADS) {
            float4 pv = buf[4 * STAGE4 + i];
            float4 a0 = buf[0 * STAGE4 + i];
            float4 a1 = buf[1 * STAGE4 + i];
            float4 a2 = buf[2 * STAGE4 + i];
            float4 a3 = buf[3 * STAGE4 + i];
            s0 += a0.x * pv.x + a0.y * pv.y + a0.z * pv.z + a0.w * pv.w;
            s1 += a1.x * pv.x + a1.y * pv.y + a1.z * pv.z + a1.w * pv.w;
            s2 += a2.x * pv.x + a2.y * pv.y + a2.z * pv.z + a2.w * pv.w;
            s3 += a3.x * pv.x + a3.y * pv.y + a3.z * pv.z + a3.w * pv.w;
        }
        __syncthreads();                       // slot free for reuse
        if (tid == 0 && s + RING < NSTAGES) issue(s + RING);
    }

    // Warp reduction of the 4 accumulators
    #pragma unroll
    for (int off = 16; off > 0; off >>= 1) {
        s0 += __shfl_xor_sync(0xFFFFFFFFu, s0, off);
        s1 += __shfl_xor_sync(0xFFFFFFFFu, s1, off);
        s2 += __shfl_xor_sync(0xFFFFFFFFu, s2, off);
        s3 += __shfl_xor_sync(0xFFFFFFFFu, s3, off);
    }

    const int lane = tid & 31;
    const int wid  = tid >> 5;
    if (lane == 0) { ws[0][wid] = s0; ws[1][wid] = s1; ws[2][wid] = s2; ws[3][wid] = s3; }
    __syncthreads();

    if (wid < RPB && lane < NWARPS) {
        float v = ws[wid][lane];
        #pragma unroll
        for (int off = NWARPS / 2; off > 0; off >>= 1)
            v += __shfl_xor_sync(0xFFFFu, v, off);
        if (lane == 0)
            g_partials[(mbase + wid) * SPLIT + chunk] = v;
    }

    // Fused final reduction: last block to finish sums the partials.
    __threadfence();
    if (tid == 0) {
        unsigned int t = atomicAdd(&g_ticket, 1u);
        s_last = (t == NBLOCKS - 1);
    }
    __syncthreads();

    if (s_last) {
        const int m = tid;
        if (m < NOUT) {
            float s = 0.0f;
            #pragma unroll
            for (int c = 0; c < SPLIT; c++)
                s += __ldcg(&g_partials[m * SPLIT + c]);
            out[m] = s;
        }
        if (tid == 0) g_ticket = 0;   // reset for next call
    }
}

extern "C" void kernel_launch(void* const* d_in, const int* in_sizes, int n_in,
                              void* d_out, int out_size)
{
    const float* p     = (const float*)d_in[0];   // [50000]
    const float* I     = (const float*)d_in[1];   // [784, 50000]
    const float* J     = (const float*)d_in[2];   // [784, 50000]
    const int*   inds1 = (const int*)  d_in[3];   // [100, 2]
    const int*   inds2 = (const int*)  d_in[4];   // [100, 2]
    float*       out   = (float*)d_out;           // [200]

    cudaFuncSetAttribute(gather_dot_v14,
                         cudaFuncAttributeMaxDynamicSharedMemorySize, SMEM_DYN);
    gather_dot_v14<<<NBLOCKS, NTHREADS, SMEM_DYN>>>(p, I, J, inds1, inds2, out);
}

// round 17
// speedup vs baseline: 1.2179x; 1.2179x over previous
#include <cuda_runtime.h>
#include <cstdint>

// out[0:100]   = dot(I[row,:], p), row = inds1[m,0]*28 + inds1[m,1]
// out[100:200] = dot(J[row,:], p), P = 50000.
//
// v15: v12 structure (100 blocks, 5 streams, RING=3, fused global-ticket
// reduction) with bursts pushed to the SMEM ceiling: 14KB per cp.async.bulk
// (STAGE4=896), 210KB dynamic SMEM. Measured gradient across v8/v12/v14:
// fewer streams + larger bursts -> higher DRAM page-hit efficiency.

#define P_DIM     50000
#define P_VEC4    (P_DIM / 4)      // 12500 float4 per row
#define SPLIT     2
#define CHUNK4    (P_VEC4 / SPLIT) // 6250 float4 per stream per block
#define STAGE4    896              // float4 per stream per stage (14KB)
#define NSTAGES   7                // 6*896 + 874
#define LAST4     (CHUNK4 - (NSTAGES - 1) * STAGE4)  // 874
#define CARD2     100
#define NOUT      200
#define RPB       4
#define NGROUPS   (NOUT / RPB)     // 50
#define NBLOCKS   (NGROUPS * SPLIT) // 100 (<= 148 -> one wave)
#define W_IMG     28
#define NTHREADS  512
#define NWARPS    16
#define NSTREAMS  (RPB + 1)
#define RING      3
#define STAGE_BYTES (STAGE4 * 16)               // 14336 B per stream
#define BUF_BYTES   (NSTREAMS * STAGE_BYTES)    // 71680 B per stage
#define SMEM_DYN    (RING * BUF_BYTES)          // 215040 B (< 227KB cap)

__device__ float        g_partials[NOUT * SPLIT];
__device__ unsigned int g_ticket = 0;

__device__ __forceinline__ uint32_t smem_u32(const void* p) {
    uint32_t a;
    asm("{ .reg .u64 t; cvta.to.shared.u64 t, %1; cvt.u32.u64 %0, t; }"
        : "=r"(a) : "l"(p));
    return a;
}
__device__ __forceinline__ void mbar_init(uint32_t bar, uint32_t cnt) {
    asm volatile("mbarrier.init.shared.b64 [%0], %1;" :: "r"(bar), "r"(cnt) : "memory");
}
__device__ __forceinline__ void mbar_expect_tx(uint32_t bar, uint32_t bytes) {
    asm volatile("mbarrier.arrive.expect_tx.shared.b64 _, [%0], %1;"
                 :: "r"(bar), "r"(bytes) : "memory");
}
__device__ __forceinline__ void mbar_wait(uint32_t bar, uint32_t parity) {
    uint32_t done;
    asm volatile(
        "{ .reg .pred p;\n"
        "  mbarrier.try_wait.parity.acquire.cta.shared::cta.b64 p, [%1], %2;\n"
        "  selp.b32 %0, 1, 0, p; }"
        : "=r"(done) : "r"(bar), "r"(parity) : "memory");
    if (!done) {
        asm volatile(
            "{ .reg .pred P1;\n"
            "WAIT_%=:\n"
            "  mbarrier.try_wait.parity.acquire.cta.shared::cta.b64 P1, [%0], %1, 0x989680;\n"
            "  @P1 bra.uni DONE_%=;\n"
            "  bra.uni WAIT_%=;\n"
            "DONE_%=: }"
            :: "r"(bar), "r"(parity) : "memory");
    }
}
__device__ __forceinline__ void bulk_g2s(uint32_t dst, const void* src,
                                         uint32_t bytes, uint32_t bar) {
    asm volatile(
        "cp.async.bulk.shared::cta.global.mbarrier::complete_tx::bytes "
        "[%0], [%1], %2, [%3];"
        :: "r"(dst), "l"(src), "r"(bytes), "r"(bar) : "memory");
}

__global__ __launch_bounds__(NTHREADS)
void gather_dot_v15(const float* __restrict__ p,
                    const float* __restrict__ I,
                    const float* __restrict__ J,
                    const int*   __restrict__ inds1,
                    const int*   __restrict__ inds2,
                    float*       __restrict__ out)
{
    extern __shared__ __align__(128) unsigned char smem[];
    __shared__ __align__(8) uint64_t mbar_storage[RING];
    __shared__ float ws[RPB][NWARPS];
    __shared__ bool  s_last;

    const int tid   = threadIdx.x;
    const int group = blockIdx.x / SPLIT;   // 0..49
    const int chunk = blockIdx.x % SPLIT;   // 0..1
    const int mbase = group * RPB;          // never straddles the I/J boundary

    const float* mat;
    const int*   ind;
    if (mbase < CARD2) { mat = I; ind = inds1 + 2 * mbase; }
    else               { mat = J; ind = inds2 + 2 * (mbase - CARD2); }

    const uint32_t sbase = smem_u32(smem);
    uint32_t bar[RING];
    #pragma unroll
    for (int k = 0; k < RING; k++) bar[k] = smem_u32(&mbar_storage[k]);

    if (tid == 0) {
        #pragma unroll
        for (int k = 0; k < RING; k++) mbar_init(bar[k], 1);
    }
    __syncthreads();

    const char* src[NSTREAMS];
    #pragma unroll
    for (int k = 0; k < RPB; k++) {
        int row = ind[2 * k] * W_IMG + ind[2 * k + 1];
        src[k] = (const char*)(mat + (size_t)row * P_DIM) + (size_t)chunk * CHUNK4 * 16;
    }
    src[RPB] = (const char*)p + (size_t)chunk * CHUNK4 * 16;

    auto issue = [&](int s) {
        const int      len   = (s == NSTAGES - 1) ? LAST4 : STAGE4;
        const uint32_t bytes = (uint32_t)len * 16u;
        const int      slot  = s % RING;
        const uint32_t dst0  = sbase + (uint32_t)slot * BUF_BYTES;
        mbar_expect_tx(bar[slot], bytes * NSTREAMS);
        #pragma unroll
        for (int k = 0; k < NSTREAMS; k++)
            bulk_g2s(dst0 + k * STAGE_BYTES, src[k] + (size_t)s * STAGE_BYTES,
                     bytes, bar[slot]);
    };

    if (tid == 0) { issue(0); issue(1); issue(2); }

    float s0 = 0.0f, s1 = 0.0f, s2 = 0.0f, s3 = 0.0f;

    for (int s = 0; s < NSTAGES; s++) {
        const int slot   = s % RING;
        const int parity = (s / RING) & 1;
        mbar_wait(bar[slot], parity);

        const int len = (s == NSTAGES - 1) ? LAST4 : STAGE4;
        const float4* buf = reinterpret_cast<const float4*>(smem + slot * BUF_BYTES);
        for (int i = tid; i < len; i += NTHREADS) {
            float4 pv = buf[4 * STAGE4 + i];
            float4 a0 = buf[0 * STAGE4 + i];
            float4 a1 = buf[1 * STAGE4 + i];
            float4 a2 = buf[2 * STAGE4 + i];
            float4 a3 = buf[3 * STAGE4 + i];
            s0 += a0.x * pv.x + a0.y * pv.y + a0.z * pv.z + a0.w * pv.w;
            s1 += a1.x * pv.x + a1.y * pv.y + a1.z * pv.z + a1.w * pv.w;
            s2 += a2.x * pv.x + a2.y * pv.y + a2.z * pv.z + a2.w * pv.w;
            s3 += a3.x * pv.x + a3.y * pv.y + a3.z * pv.z + a3.w * pv.w;
        }
        __syncthreads();                       // slot free for reuse
        if (tid == 0 && s + RING < NSTAGES) issue(s + RING);
    }

    // Warp reduction of the 4 accumulators
    #pragma unroll
    for (int off = 16; off > 0; off >>= 1) {
        s0 += __shfl_xor_sync(0xFFFFFFFFu, s0, off);
        s1 += __shfl_xor_sync(0xFFFFFFFFu, s1, off);
        s2 += __shfl_xor_sync(0xFFFFFFFFu, s2, off);
        s3 += __shfl_xor_sync(0xFFFFFFFFu, s3, off);
    }

    const int lane = tid & 31;
    const int wid  = tid >> 5;
    if (lane == 0) { ws[0][wid] = s0; ws[1][wid] = s1; ws[2][wid] = s2; ws[3][wid] = s3; }
    __syncthreads();

    if (wid < RPB && lane < NWARPS) {
        float v = ws[wid][lane];
        #pragma unroll
        for (int off = NWARPS / 2; off > 0; off >>= 1)
            v += __shfl_xor_sync(0xFFFFu, v, off);
        if (lane == 0)
            g_partials[(mbase + wid) * SPLIT + chunk] = v;
    }

    // Fused final reduction: last block to finish sums the partials.
    __threadfence();
    if (tid == 0) {
        unsigned int t = atomicAdd(&g_ticket, 1u);
        s_last = (t == NBLOCKS - 1);
    }
    __syncthreads();

    if (s_last) {
        const int m = tid;
        if (m < NOUT) {
            float s = 0.0f;
            #pragma unroll
            for (int c = 0; c < SPLIT; c++)
                s += __ldcg(&g_partials[m * SPLIT + c]);
            out[m] = s;
        }
        if (tid == 0) g_ticket = 0;   // reset for next call
    }
}

extern "C" void kernel_launch(void* const* d_in, const int* in_sizes, int n_in,
                              void* d_out, int out_size)
{
    const float* p     = (const float*)d_in[0];   // [50000]
    const float* I     = (const float*)d_in[1];   // [784, 50000]
    const float* J     = (const float*)d_in[2];   // [784, 50000]
    const int*   inds1 = (const int*)  d_in[3];   // [100, 2]
    const int*   inds2 = (const int*)  d_in[4];   // [100, 2]
    float*       out   = (float*)d_out;           // [200]

    cudaFuncSetAttribute(gather_dot_v15,
                         cudaFuncAttributeMaxDynamicSharedMemorySize, SMEM_DYN);
    gather_dot_v15<<<NBLOCKS, NTHREADS, SMEM_DYN>>>(p, I, J, inds1, inds2, out);
}